// round 10
// baseline (speedup 1.0000x reference)
#include <cuda_runtime.h>
#include <cstdint>

#define F_IN   8192
#define F_OUT  16384
#define BATCH  32
#define HEADS  512

// Scratch (static __device__ — allocation-free per harness rules)
__device__ float g_xr[BATCH * F_IN];    // tf32(RNA)-rounded x
__device__ float g_q[BATCH * F_OUT];
__device__ float g_k[BATCH * F_OUT];
__device__ float g_v[BATCH * F_OUT];
__device__ float g_rzt[BATCH * 32 * 32]; // 1/Z transposed: [b][j][i]

__device__ __forceinline__ uint32_t tf32_rna(float f) {
    uint32_t u;
    asm("cvt.rna.tf32.f32 %0, %1;" : "=r"(u) : "f"(f));
    return u;
}

__device__ __forceinline__ float gelu_exact(float v) {
    return 0.5f * v * (1.0f + erff(v * 0.70710678118654752f));
}

// ---------------------------------------------------------------------------
// Kernel 0: pre-round x to tf32 (RNA) once. Vectorized float4.
// ---------------------------------------------------------------------------
__global__ void round_x_kernel(const float4* __restrict__ x) {
    int i = blockIdx.x * blockDim.x + threadIdx.x;
    float4 v = x[i];
    float4 o;
    o.x = __uint_as_float(tf32_rna(v.x));
    o.y = __uint_as_float(tf32_rna(v.y));
    o.z = __uint_as_float(tf32_rna(v.z));
    o.w = __uint_as_float(tf32_rna(v.w));
    reinterpret_cast<float4*>(g_xr)[i] = o;
}

// ---------------------------------------------------------------------------
// Kernel 1: QKV GEMM, transposed: D^T[m][b] = sum_k W[m][k]*x[b][k]
// KC=64 EXPERIMENT: each W row is read as one 256B contiguous burst per
// chunk (vs 128B at R5's KC=32) -> double DRAM payload per page activate.
// R6 profile showed DRAM 72.9% eff; the 128B-at-32KB-stride pattern (next
// 128B of a row requested ~2000cyc later, page closed) is the suspected
// cause. Everything else is R5 verbatim: 128 thr / 4 warps, warp m32n32,
// stage-after-compute. 2 stages x 46080B = 92160B -> occ 2. In the pure
// BW-bound regime the lost one-wave residency is acceptable (the 88-CTA
// tail still saturates DRAM by Little's law).
// k-permutation inside each k8 (logical tq -> phys 2tq, tq+4 -> 2tq+1) on
// BOTH operands => aligned LDS.64 fragments; RS=72 gives the same
// 16-lane-phase-clean bank mapping as the proven RS=40.
// ---------------------------------------------------------------------------
#define MMA_TF32(d, a0,a1,a2,a3, b0,b1)                                     \
    asm volatile("mma.sync.aligned.m16n8k8.row.col.f32.tf32.tf32.f32 "      \
        "{%0,%1,%2,%3}, {%4,%5,%6,%7}, {%8,%9}, {%0,%1,%2,%3};"             \
        : "+f"(d[0]), "+f"(d[1]), "+f"(d[2]), "+f"(d[3])                    \
        : "r"(a0), "r"(a1), "r"(a2), "r"(a3), "r"(b0), "r"(b1))

#define KC        64            // K-chunk (256B per W row per chunk)
#define RS        72            // row stride in floats (64 + 8 pad)
#define MT        128           // CTA M-tile (rows of W)
#define NSTAGE    2
#define WSF       (MT * RS)     // 9216 floats per W stage
#define XSF       (BATCH * RS)  // 2304 floats per x stage
#define STAGEF    (WSF + XSF)   // 11520 floats = 46080 B per stage
#define SMEM_BYTES (NSTAGE * STAGEF * 4)   // 92160 B

__device__ __forceinline__ void cp16(float* dst, const float* src) {
    uint32_t d = (uint32_t)__cvta_generic_to_shared(dst);
    asm volatile("cp.async.cg.shared.global [%0], [%1], 16;" :: "r"(d), "l"(src));
}

__global__ __launch_bounds__(128, 2)
void qkv_gemm_kernel(const float* __restrict__ Wq, const float* __restrict__ bq,
                     const float* __restrict__ Wk, const float* __restrict__ bk,
                     const float* __restrict__ Wv, const float* __restrict__ bv) {
    extern __shared__ float smem[];

    const float* W; const float* bias; float* out;
    if (blockIdx.y == 0)      { W = Wq; bias = bq; out = g_q; }
    else if (blockIdx.y == 1) { W = Wk; bias = bk; out = g_k; }
    else                      { W = Wv; bias = bv; out = g_v; }

    const int tid  = threadIdx.x;
    const int warp = tid >> 5;
    const int lane = tid & 31;
    const int g    = lane >> 2;       // groupID (0..7)
    const int tq   = lane & 3;        // thread-in-group (0..3)
    const int mb   = blockIdx.x * MT; // CTA's first W row

    float acc[2][4][4];               // [m16-subtile][n-tile(batch/8)][frag]
    #pragma unroll
    for (int a = 0; a < 2; a++)
        #pragma unroll
        for (int b = 0; b < 4; b++)
            #pragma unroll
            for (int r = 0; r < 4; r++) acc[a][b][r] = 0.0f;

    // stage one K-chunk: W tile 128x64 (256B bursts/row) + x tile 32x64
    auto stage = [&](int s, int c) {
        float* ws = smem + s * STAGEF;
        float* xs = ws + WSF;
        const int kc = c * KC;
        #pragma unroll
        for (int r = 0; r < 16; r++) {
            int idx = tid + r * 128;            // 2048 float4
            int row = idx >> 4;
            int c4  = idx & 15;
            cp16(&ws[row * RS + c4 * 4],
                 W + (size_t)(mb + row) * F_IN + kc + c4 * 4);
        }
        #pragma unroll
        for (int r = 0; r < 4; r++) {
            int idx = tid + r * 128;            // 512 float4
            int b   = idx >> 4;
            int c4  = idx & 15;
            cp16(&xs[b * RS + c4 * 4],
                 g_xr + (size_t)b * F_IN + kc + c4 * 4);
        }
        asm volatile("cp.async.commit_group;");
    };

    stage(0, 0); stage(1, 1);

    const int NCHUNK = F_IN / KC;     // 128
    for (int c = 0; c < NCHUNK; c++) {
        if (c + 1 < NCHUNK) asm volatile("cp.async.wait_group 1;");
        else                asm volatile("cp.async.wait_group 0;");
        __syncthreads();

        const float* ws = smem + (c & 1) * STAGEF;
        const float* xs = ws + WSF;

        #pragma unroll
        for (int s = 0; s < 8; s++) {
            const int kp = 8 * s + 2 * tq;    // physical k offset in chunk

            // A (W) fragments: two m16 subtiles, rows warp*32 + {g,g+8,g+16,g+24}
            uint32_t A[2][4];
            #pragma unroll
            for (int mt = 0; mt < 2; mt++) {
                const int r0 = warp * 32 + mt * 16 + g;
                float2 lo = *reinterpret_cast<const float2*>(&ws[r0 * RS + kp]);
                float2 hi = *reinterpret_cast<const float2*>(&ws[(r0 + 8) * RS + kp]);
                A[mt][0] = tf32_rna(lo.x);   // a0: (m=g,   k'=tq)
                A[mt][1] = tf32_rna(hi.x);   // a1: (m=g+8, k'=tq)
                A[mt][2] = tf32_rna(lo.y);   // a2: (m=g,   k'=tq+4)
                A[mt][3] = tf32_rna(hi.y);   // a3: (m=g+8, k'=tq+4)
            }

            // B (x^T) fragments: n = batch, 4 n-tiles of 8 (already tf32)
            float2 bvf[4];
            #pragma unroll
            for (int j = 0; j < 4; j++)
                bvf[j] = *reinterpret_cast<const float2*>(&xs[(j * 8 + g) * RS + kp]);

            #pragma unroll
            for (int mt = 0; mt < 2; mt++)
                #pragma unroll
                for (int j = 0; j < 4; j++)
                    MMA_TF32(acc[mt][j], A[mt][0], A[mt][1], A[mt][2], A[mt][3],
                             __float_as_uint(bvf[j].x), __float_as_uint(bvf[j].y));
        }

        __syncthreads();                      // all reads of buf done
        if (c + NSTAGE < NCHUNK) stage(c & 1, c + NSTAGE);
    }

    // Epilogue: bias + exact GELU, store transposed into [batch][F_OUT]
    #pragma unroll
    for (int mt = 0; mt < 2; mt++) {
        const int r0 = mb + warp * 32 + mt * 16 + g;   // output feature index
        const float bia0 = bias[r0];
        const float bia1 = bias[r0 + 8];
        #pragma unroll
        for (int j = 0; j < 4; j++) {
            const int bt = j * 8 + 2 * tq;             // batch index
            out[(size_t)bt       * F_OUT + r0    ] = gelu_exact(acc[mt][j][0] + bia0);
            out[(size_t)(bt + 1) * F_OUT + r0    ] = gelu_exact(acc[mt][j][1] + bia0);
            out[(size_t)bt       * F_OUT + r0 + 8] = gelu_exact(acc[mt][j][2] + bia1);
            out[(size_t)(bt + 1) * F_OUT + r0 + 8] = gelu_exact(acc[mt][j][3] + bia1);
        }
    }
}

// ---------------------------------------------------------------------------
// Kernel 2: softmax denominators over the HEADS axis (bias cancels).
// rZt[b][j][i] = 1 / sum_h exp(c * q[b,h,i] * k[b,h,j])   (R5 version)
// ---------------------------------------------------------------------------
#define ATTN_SCALE 0.17677669529663687f   // 1/sqrt(32)

__global__ void attn_z_kernel() {
    const int b  = blockIdx.x;
    const int iq = blockIdx.y;
    const int tid = threadIdx.x;
    const int il  = tid >> 5;
    const int j   = tid & 31;
    const int i   = iq * 8 + il;

    __shared__ float qs[32][8];
    __shared__ float ks[32][32];

    const float* __restrict__ qb = g_q + (size_t)b * F_OUT;
    const float* __restrict__ kb = g_k + (size_t)b * F_OUT;

    float z = 0.0f;
    for (int hc = 0; hc < 16; hc++) {
        {
            int hh = tid >> 3, ii = tid & 7;
            qs[hh][ii] = qb[(size_t)(hc * 32 + hh) * 32 + iq * 8 + ii];
            #pragma unroll
            for (int r = 0; r < 4; r++) {
                int idx = tid + r * 256;
                int hh2 = idx >> 5, jj = idx & 31;
                ks[hh2][jj] = kb[(size_t)(hc * 32 + hh2) * 32 + jj];
            }
        }
        __syncthreads();
        #pragma unroll
        for (int hh = 0; hh < 32; hh++)
            z += __expf(ATTN_SCALE * qs[hh][il] * ks[hh][j]);
        __syncthreads();
    }
    g_rzt[(size_t)b * 1024 + j * 32 + i] = 1.0f / z;
}

// ---------------------------------------------------------------------------
// Kernel 3: out[b,h,i] = sum_j exp(c*q_i*k_j) * rZ[b,i,j] * v[b,h,j]
// (k,v) staged in SMEM as float2 (LDS.64 broadcast per j),
// rz tile staged in SMEM.
// ---------------------------------------------------------------------------
__global__ void attn_o_kernel(float* __restrict__ out) {
    __shared__ float2 kvs[8][32];
    __shared__ float  rzs[1024];

    const int b    = blockIdx.y;
    const int tid  = threadIdx.x;
    const int wl   = tid >> 5;
    const int lane = tid & 31;
    const int h    = blockIdx.x * 8 + wl;

    const size_t base = (size_t)b * F_OUT + (size_t)h * 32;

    {
        float kk = g_k[base + lane];
        float vv = g_v[base + lane];
        kvs[wl][lane] = make_float2(kk, vv);
        #pragma unroll
        for (int r = 0; r < 4; r++)
            rzs[tid + r * 256] = g_rzt[(size_t)b * 1024 + tid + r * 256];
    }
    const float qv = g_q[base + lane] * ATTN_SCALE;
    __syncthreads();

    float accv = 0.0f;
    #pragma unroll
    for (int j = 0; j < 32; j++) {
        float2 kv = kvs[wl][j];                 // LDS.64 broadcast
        accv += __expf(qv * kv.x) * kv.y * rzs[j * 32 + lane];
    }
    out[((size_t)b * HEADS + h) * 32 + lane] = accv;
}

// ---------------------------------------------------------------------------
extern "C" void kernel_launch(void* const* d_in, const int* in_sizes, int n_in,
                              void* d_out, int out_size) {
    const float* x  = (const float*)d_in[0];
    const float* Wq = (const float*)d_in[1];
    const float* bq = (const float*)d_in[2];
    const float* Wk = (const float*)d_in[3];
    const float* bk = (const float*)d_in[4];
    const float* Wv = (const float*)d_in[5];
    const float* bv = (const float*)d_in[6];
    // d_in[7] (tw): constant along softmax axis (heads) -> cancels; unused.
    (void)in_sizes; (void)n_in; (void)out_size;

    cudaFuncSetAttribute(qkv_gemm_kernel,
                         cudaFuncAttributeMaxDynamicSharedMemorySize, SMEM_BYTES);

    round_x_kernel<<<256, 256>>>((const float4*)x);
    qkv_gemm_kernel<<<dim3(F_OUT / MT, 3), 128, SMEM_BYTES>>>(Wq, bq, Wk, bk, Wv, bv);
    attn_z_kernel<<<dim3(32, 4), 256>>>();
    attn_o_kernel<<<dim3(64, 32), 256>>>((float*)d_out);
}

// round 11
// speedup vs baseline: 1.1936x; 1.1936x over previous
#include <cuda_runtime.h>
#include <cstdint>

#define F_IN   8192
#define F_OUT  16384
#define BATCH  32
#define HEADS  512

// Scratch (static __device__ — allocation-free per harness rules)
__device__ float g_xr[BATCH * F_IN];    // tf32(RNA)-rounded x
__device__ float g_q[BATCH * F_OUT];
__device__ float g_k[BATCH * F_OUT];
__device__ float g_v[BATCH * F_OUT];
__device__ float g_rzt[BATCH * 32 * 32]; // 1/Z transposed: [b][j][i]

__device__ __forceinline__ uint32_t tf32_rna(float f) {
    uint32_t u;
    asm("cvt.rna.tf32.f32 %0, %1;" : "=r"(u) : "f"(f));
    return u;
}

__device__ __forceinline__ float ex2(float x) {
    float r;
    asm("ex2.approx.f32 %0, %1;" : "=f"(r) : "f"(x));
    return r;
}

__device__ __forceinline__ float gelu_exact(float v) {
    return 0.5f * v * (1.0f + erff(v * 0.70710678118654752f));
}

// ---------------------------------------------------------------------------
// Kernel 0: pre-round x to tf32 (RNA) once. Vectorized float4.
// ---------------------------------------------------------------------------
__global__ void round_x_kernel(const float4* __restrict__ x) {
    int i = blockIdx.x * blockDim.x + threadIdx.x;
    float4 v = x[i];
    float4 o;
    o.x = __uint_as_float(tf32_rna(v.x));
    o.y = __uint_as_float(tf32_rna(v.y));
    o.z = __uint_as_float(tf32_rna(v.z));
    o.w = __uint_as_float(tf32_rna(v.w));
    reinterpret_cast<float4*>(g_xr)[i] = o;
}

// ---------------------------------------------------------------------------
// Kernel 1: QKV GEMM (R5-proven config, byte-identical pipeline).
// Transposed: D^T[m][b] = sum_k W[m][k]*x[b][k]
//   A (M-side) = W  : streamed, coalesced cp.async -> SMEM (read once)
//   B (N-side) = x^T: tiny, staged per chunk (pre-rounded to tf32)
// CTA: 128 thr / 4 warps, M-tile 128 (warp m32n32), N=32, K-chunk 32,
// 3 stages, wait_group 2 steady-state, stage AFTER compute.
// Grid 384 CTAs @ occ 3 -> all resident in ONE wave.
// k-permutation inside each k8 (logical tq -> phys 2tq, tq+4 -> 2tq+1) on
// BOTH operands => aligned LDS.64 fragments, conflict-free (RS=40 pad).
// ---------------------------------------------------------------------------
#define MMA_TF32(d, a0,a1,a2,a3, b0,b1)                                     \
    asm volatile("mma.sync.aligned.m16n8k8.row.col.f32.tf32.tf32.f32 "      \
        "{%0,%1,%2,%3}, {%4,%5,%6,%7}, {%8,%9}, {%0,%1,%2,%3};"             \
        : "+f"(d[0]), "+f"(d[1]), "+f"(d[2]), "+f"(d[3])                    \
        : "r"(a0), "r"(a1), "r"(a2), "r"(a3), "r"(b0), "r"(b1))

#define KC        32            // K-chunk
#define RS        40            // row stride in floats (32 + 8 pad)
#define MT        128           // CTA M-tile (rows of W)
#define NSTAGE    3
#define WSF       (MT * RS)     // 5120 floats per W stage
#define XSF       (BATCH * RS)  // 1280 floats per x stage
#define STAGEF    (WSF + XSF)   // 6400 floats per stage
#define SMEM_BYTES (NSTAGE * STAGEF * 4)   // 76800 B

__device__ __forceinline__ void cp16(float* dst, const float* src) {
    uint32_t d = (uint32_t)__cvta_generic_to_shared(dst);
    asm volatile("cp.async.cg.shared.global [%0], [%1], 16;" :: "r"(d), "l"(src));
}

__global__ __launch_bounds__(128, 3)
void qkv_gemm_kernel(const float* __restrict__ Wq, const float* __restrict__ bq,
                     const float* __restrict__ Wk, const float* __restrict__ bk,
                     const float* __restrict__ Wv, const float* __restrict__ bv) {
    extern __shared__ float smem[];

    const float* W; const float* bias; float* out;
    if (blockIdx.y == 0)      { W = Wq; bias = bq; out = g_q; }
    else if (blockIdx.y == 1) { W = Wk; bias = bk; out = g_k; }
    else                      { W = Wv; bias = bv; out = g_v; }

    const int tid  = threadIdx.x;
    const int warp = tid >> 5;
    const int lane = tid & 31;
    const int g    = lane >> 2;       // groupID (0..7)
    const int tq   = lane & 3;        // thread-in-group (0..3)
    const int mb   = blockIdx.x * MT; // CTA's first W row

    float acc[2][4][4];               // [m16-subtile][n-tile(batch/8)][frag]
    #pragma unroll
    for (int a = 0; a < 2; a++)
        #pragma unroll
        for (int b = 0; b < 4; b++)
            #pragma unroll
            for (int r = 0; r < 4; r++) acc[a][b][r] = 0.0f;

    // stage one K-chunk: W tile 128x32 + x tile 32x32, both coalesced
    auto stage = [&](int s, int c) {
        float* ws = smem + s * STAGEF;
        float* xs = ws + WSF;
        const int kc = c * KC;
        #pragma unroll
        for (int r = 0; r < 8; r++) {
            int idx = tid + r * 128;            // 1024 float4
            int row = idx >> 3;
            int c4  = idx & 7;
            cp16(&ws[row * RS + c4 * 4],
                 W + (size_t)(mb + row) * F_IN + kc + c4 * 4);
        }
        #pragma unroll
        for (int r = 0; r < 2; r++) {
            int idx = tid + r * 128;            // 256 float4
            int b   = idx >> 3;
            int c4  = idx & 7;
            cp16(&xs[b * RS + c4 * 4],
                 g_xr + (size_t)b * F_IN + kc + c4 * 4);
        }
        asm volatile("cp.async.commit_group;");
    };

    stage(0, 0); stage(1, 1); stage(2, 2);

    const int NCHUNK = F_IN / KC;     // 256
    for (int c = 0; c < NCHUNK; c++) {
        const int rem = NCHUNK - 1 - c;
        if (rem >= 2)      asm volatile("cp.async.wait_group 2;");
        else if (rem == 1) asm volatile("cp.async.wait_group 1;");
        else               asm volatile("cp.async.wait_group 0;");
        __syncthreads();

        const float* ws = smem + (c % NSTAGE) * STAGEF;
        const float* xs = ws + WSF;

        #pragma unroll
        for (int s = 0; s < 4; s++) {
            const int kp = 8 * s + 2 * tq;    // physical k offset in chunk

            // A (W) fragments: two m16 subtiles, rows warp*32 + {g,g+8,g+16,g+24}
            uint32_t A[2][4];
            #pragma unroll
            for (int mt = 0; mt < 2; mt++) {
                const int r0 = warp * 32 + mt * 16 + g;
                float2 lo = *reinterpret_cast<const float2*>(&ws[r0 * RS + kp]);
                float2 hi = *reinterpret_cast<const float2*>(&ws[(r0 + 8) * RS + kp]);
                A[mt][0] = tf32_rna(lo.x);   // a0: (m=g,   k'=tq)
                A[mt][1] = tf32_rna(hi.x);   // a1: (m=g+8, k'=tq)
                A[mt][2] = tf32_rna(lo.y);   // a2: (m=g,   k'=tq+4)
                A[mt][3] = tf32_rna(hi.y);   // a3: (m=g+8, k'=tq+4)
            }

            // B (x^T) fragments: n = batch, 4 n-tiles of 8 (already tf32)
            float2 bvf[4];
            #pragma unroll
            for (int j = 0; j < 4; j++)
                bvf[j] = *reinterpret_cast<const float2*>(&xs[(j * 8 + g) * RS + kp]);

            #pragma unroll
            for (int mt = 0; mt < 2; mt++)
                #pragma unroll
                for (int j = 0; j < 4; j++)
                    MMA_TF32(acc[mt][j], A[mt][0], A[mt][1], A[mt][2], A[mt][3],
                             __float_as_uint(bvf[j].x), __float_as_uint(bvf[j].y));
        }

        __syncthreads();                      // all reads of buf done
        if (c + NSTAGE < NCHUNK) stage(c % NSTAGE, c + NSTAGE);
    }

    // Epilogue: bias + exact GELU, store transposed into [batch][F_OUT]
    #pragma unroll
    for (int mt = 0; mt < 2; mt++) {
        const int r0 = mb + warp * 32 + mt * 16 + g;   // output feature index
        const float bia0 = bias[r0];
        const float bia1 = bias[r0 + 8];
        #pragma unroll
        for (int j = 0; j < 4; j++) {
            const int bt = j * 8 + 2 * tq;             // batch index
            out[(size_t)bt       * F_OUT + r0    ] = gelu_exact(acc[mt][j][0] + bia0);
            out[(size_t)(bt + 1) * F_OUT + r0    ] = gelu_exact(acc[mt][j][1] + bia0);
            out[(size_t)bt       * F_OUT + r0 + 8] = gelu_exact(acc[mt][j][2] + bia1);
            out[(size_t)(bt + 1) * F_OUT + r0 + 8] = gelu_exact(acc[mt][j][3] + bia1);
        }
    }
}

// ---------------------------------------------------------------------------
// Kernel 2: softmax denominators over the HEADS axis (bias cancels).
// rZt[b][j][i] = 1 / sum_h exp(c * q[b,h,i] * k[b,h,j])
// exp strength-reduced: qs staged pre-scaled by c*log2(e), inner loop is
// FMUL + EX2 + FADD (vs FMUL+FMUL+EX2+FADD with __expf).
// ---------------------------------------------------------------------------
#define ATTN_SCALE 0.17677669529663687f   // 1/sqrt(32)
#define SCALE_L2E  (0.17677669529663687f * 1.4426950408889634f)

__global__ void attn_z_kernel() {
    const int b  = blockIdx.x;
    const int iq = blockIdx.y;
    const int tid = threadIdx.x;
    const int il  = tid >> 5;
    const int j   = tid & 31;
    const int i   = iq * 8 + il;

    __shared__ float qs[32][8];
    __shared__ float ks[32][32];

    const float* __restrict__ qb = g_q + (size_t)b * F_OUT;
    const float* __restrict__ kb = g_k + (size_t)b * F_OUT;

    float z = 0.0f;
    for (int hc = 0; hc < 16; hc++) {
        {
            int hh = tid >> 3, ii = tid & 7;
            qs[hh][ii] = qb[(size_t)(hc * 32 + hh) * 32 + iq * 8 + ii] * SCALE_L2E;
            #pragma unroll
            for (int r = 0; r < 4; r++) {
                int idx = tid + r * 256;
                int hh2 = idx >> 5, jj = idx & 31;
                ks[hh2][jj] = kb[(size_t)(hc * 32 + hh2) * 32 + jj];
            }
        }
        __syncthreads();
        #pragma unroll
        for (int hh = 0; hh < 32; hh++)
            z += ex2(qs[hh][il] * ks[hh][j]);
        __syncthreads();
    }
    g_rzt[(size_t)b * 1024 + j * 32 + i] = 1.0f / z;
}

// ---------------------------------------------------------------------------
// Kernel 3: out[b,h,i] = sum_j exp(c*q_i*k_j) * rZ[b,i,j] * v[b,h,j]
// (k,v) staged in SMEM as float2 (LDS.64 broadcast per j), rz tile staged.
// q pre-scaled by c*log2(e): inner is FMUL + EX2 + FMUL + FFMA.
// ---------------------------------------------------------------------------
__global__ void attn_o_kernel(float* __restrict__ out) {
    __shared__ float2 kvs[8][32];
    __shared__ float  rzs[1024];

    const int b    = blockIdx.y;
    const int tid  = threadIdx.x;
    const int wl   = tid >> 5;
    const int lane = tid & 31;
    const int h    = blockIdx.x * 8 + wl;

    const size_t base = (size_t)b * F_OUT + (size_t)h * 32;

    {
        float kk = g_k[base + lane];
        float vv = g_v[base + lane];
        kvs[wl][lane] = make_float2(kk, vv);
        #pragma unroll
        for (int r = 0; r < 4; r++)
            rzs[tid + r * 256] = g_rzt[(size_t)b * 1024 + tid + r * 256];
    }
    const float qv = g_q[base + lane] * SCALE_L2E;
    __syncthreads();

    float accv = 0.0f;
    #pragma unroll
    for (int j = 0; j < 32; j++) {
        float2 kv = kvs[wl][j];                 // LDS.64 broadcast
        accv += ex2(qv * kv.x) * kv.y * rzs[j * 32 + lane];
    }
    out[((size_t)b * HEADS + h) * 32 + lane] = accv;
}

// ---------------------------------------------------------------------------
extern "C" void kernel_launch(void* const* d_in, const int* in_sizes, int n_in,
                              void* d_out, int out_size) {
    const float* x  = (const float*)d_in[0];
    const float* Wq = (const float*)d_in[1];
    const float* bq = (const float*)d_in[2];
    const float* Wk = (const float*)d_in[3];
    const float* bk = (const float*)d_in[4];
    const float* Wv = (const float*)d_in[5];
    const float* bv = (const float*)d_in[6];
    // d_in[7] (tw): constant along softmax axis (heads) -> cancels; unused.
    (void)in_sizes; (void)n_in; (void)out_size;

    cudaFuncSetAttribute(qkv_gemm_kernel,
                         cudaFuncAttributeMaxDynamicSharedMemorySize, SMEM_BYTES);

    round_x_kernel<<<256, 256>>>((const float4*)x);
    qkv_gemm_kernel<<<dim3(F_OUT / MT, 3), 128, SMEM_BYTES>>>(Wq, bq, Wk, bk, Wv, bv);
    attn_z_kernel<<<dim3(32, 4), 256>>>();
    attn_o_kernel<<<dim3(64, 32), 256>>>((float*)d_out);
}

// round 12
// speedup vs baseline: 1.2840x; 1.0757x over previous
#include <cuda_runtime.h>
#include <cstdint>

#define F_IN   8192
#define F_OUT  16384
#define BATCH  32
#define HEADS  512

// Scratch (static __device__ — allocation-free per harness rules)
__device__ float g_xr[BATCH * F_IN];    // tf32(RNA)-rounded x
__device__ float g_q[BATCH * F_OUT];
__device__ float g_k[BATCH * F_OUT];
__device__ float g_v[BATCH * F_OUT];
__device__ float g_rzt[BATCH * 32 * 32]; // 1/Z transposed: [b][j][i]

__device__ __forceinline__ uint32_t tf32_rna(float f) {
    uint32_t u;
    asm("cvt.rna.tf32.f32 %0, %1;" : "=r"(u) : "f"(f));
    return u;
}

__device__ __forceinline__ float gelu_exact(float v) {
    return 0.5f * v * (1.0f + erff(v * 0.70710678118654752f));
}

// ---------------------------------------------------------------------------
// Kernel 0: pre-round x to tf32 (RNA) once. Vectorized float4.
// ---------------------------------------------------------------------------
__global__ void round_x_kernel(const float4* __restrict__ x) {
    int i = blockIdx.x * blockDim.x + threadIdx.x;
    float4 v = x[i];
    float4 o;
    o.x = __uint_as_float(tf32_rna(v.x));
    o.y = __uint_as_float(tf32_rna(v.y));
    o.z = __uint_as_float(tf32_rna(v.z));
    o.w = __uint_as_float(tf32_rna(v.w));
    reinterpret_cast<float4*>(g_xr)[i] = o;
}

// ---------------------------------------------------------------------------
// Kernel 1: QKV GEMM (R5-proven config — best measured: 291.0us total).
// Transposed: D^T[m][b] = sum_k W[m][k]*x[b][k]
//   A (M-side) = W  : streamed, coalesced cp.async -> SMEM (read once)
//   B (N-side) = x^T: tiny, staged per chunk (pre-rounded to tf32)
// CTA: 128 thr / 4 warps, M-tile 128 (warp m32n32), N=32, K-chunk 32,
// 3 stages, wait_group 2 steady-state, stage AFTER compute.
// Grid 384 CTAs @ occ 3 -> all resident in ONE wave.
// k-permutation inside each k8 (logical tq -> phys 2tq, tq+4 -> 2tq+1) on
// BOTH operands => aligned LDS.64 fragments, conflict-free (RS=40 pad).
// ---------------------------------------------------------------------------
#define MMA_TF32(d, a0,a1,a2,a3, b0,b1)                                     \
    asm volatile("mma.sync.aligned.m16n8k8.row.col.f32.tf32.tf32.f32 "      \
        "{%0,%1,%2,%3}, {%4,%5,%6,%7}, {%8,%9}, {%0,%1,%2,%3};"             \
        : "+f"(d[0]), "+f"(d[1]), "+f"(d[2]), "+f"(d[3])                    \
        : "r"(a0), "r"(a1), "r"(a2), "r"(a3), "r"(b0), "r"(b1))

#define KC        32            // K-chunk
#define RS        40            // row stride in floats (32 + 8 pad)
#define MT        128           // CTA M-tile (rows of W)
#define NSTAGE    3
#define WSF       (MT * RS)     // 5120 floats per W stage
#define XSF       (BATCH * RS)  // 1280 floats per x stage
#define STAGEF    (WSF + XSF)   // 6400 floats per stage
#define SMEM_BYTES (NSTAGE * STAGEF * 4)   // 76800 B

__device__ __forceinline__ void cp16(float* dst, const float* src) {
    uint32_t d = (uint32_t)__cvta_generic_to_shared(dst);
    asm volatile("cp.async.cg.shared.global [%0], [%1], 16;" :: "r"(d), "l"(src));
}

__global__ __launch_bounds__(128, 3)
void qkv_gemm_kernel(const float* __restrict__ Wq, const float* __restrict__ bq,
                     const float* __restrict__ Wk, const float* __restrict__ bk,
                     const float* __restrict__ Wv, const float* __restrict__ bv) {
    extern __shared__ float smem[];

    const float* W; const float* bias; float* out;
    if (blockIdx.y == 0)      { W = Wq; bias = bq; out = g_q; }
    else if (blockIdx.y == 1) { W = Wk; bias = bk; out = g_k; }
    else                      { W = Wv; bias = bv; out = g_v; }

    const int tid  = threadIdx.x;
    const int warp = tid >> 5;
    const int lane = tid & 31;
    const int g    = lane >> 2;       // groupID (0..7)
    const int tq   = lane & 3;        // thread-in-group (0..3)
    const int mb   = blockIdx.x * MT; // CTA's first W row

    float acc[2][4][4];               // [m16-subtile][n-tile(batch/8)][frag]
    #pragma unroll
    for (int a = 0; a < 2; a++)
        #pragma unroll
        for (int b = 0; b < 4; b++)
            #pragma unroll
            for (int r = 0; r < 4; r++) acc[a][b][r] = 0.0f;

    // stage one K-chunk: W tile 128x32 + x tile 32x32, both coalesced
    auto stage = [&](int s, int c) {
        float* ws = smem + s * STAGEF;
        float* xs = ws + WSF;
        const int kc = c * KC;
        #pragma unroll
        for (int r = 0; r < 8; r++) {
            int idx = tid + r * 128;            // 1024 float4
            int row = idx >> 3;
            int c4  = idx & 7;
            cp16(&ws[row * RS + c4 * 4],
                 W + (size_t)(mb + row) * F_IN + kc + c4 * 4);
        }
        #pragma unroll
        for (int r = 0; r < 2; r++) {
            int idx = tid + r * 128;            // 256 float4
            int b   = idx >> 3;
            int c4  = idx & 7;
            cp16(&xs[b * RS + c4 * 4],
                 g_xr + (size_t)b * F_IN + kc + c4 * 4);
        }
        asm volatile("cp.async.commit_group;");
    };

    stage(0, 0); stage(1, 1); stage(2, 2);

    const int NCHUNK = F_IN / KC;     // 256
    for (int c = 0; c < NCHUNK; c++) {
        const int rem = NCHUNK - 1 - c;
        if (rem >= 2)      asm volatile("cp.async.wait_group 2;");
        else if (rem == 1) asm volatile("cp.async.wait_group 1;");
        else               asm volatile("cp.async.wait_group 0;");
        __syncthreads();

        const float* ws = smem + (c % NSTAGE) * STAGEF;
        const float* xs = ws + WSF;

        #pragma unroll
        for (int s = 0; s < 4; s++) {
            const int kp = 8 * s + 2 * tq;    // physical k offset in chunk

            // A (W) fragments: two m16 subtiles, rows warp*32 + {g,g+8,g+16,g+24}
            uint32_t A[2][4];
            #pragma unroll
            for (int mt = 0; mt < 2; mt++) {
                const int r0 = warp * 32 + mt * 16 + g;
                float2 lo = *reinterpret_cast<const float2*>(&ws[r0 * RS + kp]);
                float2 hi = *reinterpret_cast<const float2*>(&ws[(r0 + 8) * RS + kp]);
                A[mt][0] = tf32_rna(lo.x);   // a0: (m=g,   k'=tq)
                A[mt][1] = tf32_rna(hi.x);   // a1: (m=g+8, k'=tq)
                A[mt][2] = tf32_rna(lo.y);   // a2: (m=g,   k'=tq+4)
                A[mt][3] = tf32_rna(hi.y);   // a3: (m=g+8, k'=tq+4)
            }

            // B (x^T) fragments: n = batch, 4 n-tiles of 8 (already tf32)
            float2 bvf[4];
            #pragma unroll
            for (int j = 0; j < 4; j++)
                bvf[j] = *reinterpret_cast<const float2*>(&xs[(j * 8 + g) * RS + kp]);

            #pragma unroll
            for (int mt = 0; mt < 2; mt++)
                #pragma unroll
                for (int j = 0; j < 4; j++)
                    MMA_TF32(acc[mt][j], A[mt][0], A[mt][1], A[mt][2], A[mt][3],
                             __float_as_uint(bvf[j].x), __float_as_uint(bvf[j].y));
        }

        __syncthreads();                      // all reads of buf done
        if (c + NSTAGE < NCHUNK) stage(c % NSTAGE, c + NSTAGE);
    }

    // Epilogue: bias + exact GELU, store transposed into [batch][F_OUT]
    #pragma unroll
    for (int mt = 0; mt < 2; mt++) {
        const int r0 = mb + warp * 32 + mt * 16 + g;   // output feature index
        const float bia0 = bias[r0];
        const float bia1 = bias[r0 + 8];
        #pragma unroll
        for (int j = 0; j < 4; j++) {
            const int bt = j * 8 + 2 * tq;             // batch index
            out[(size_t)bt       * F_OUT + r0    ] = gelu_exact(acc[mt][j][0] + bia0);
            out[(size_t)(bt + 1) * F_OUT + r0    ] = gelu_exact(acc[mt][j][1] + bia0);
            out[(size_t)bt       * F_OUT + r0 + 8] = gelu_exact(acc[mt][j][2] + bia1);
            out[(size_t)(bt + 1) * F_OUT + r0 + 8] = gelu_exact(acc[mt][j][3] + bia1);
        }
    }
}

// ---------------------------------------------------------------------------
// Kernel 2: softmax denominators over the HEADS axis (bias cancels).
// rZt[b][j][i] = 1 / sum_h exp(c * q[b,h,i] * k[b,h,j])
// ---------------------------------------------------------------------------
#define ATTN_SCALE 0.17677669529663687f   // 1/sqrt(32)

__global__ void attn_z_kernel() {
    const int b  = blockIdx.x;
    const int iq = blockIdx.y;
    const int tid = threadIdx.x;
    const int il  = tid >> 5;
    const int j   = tid & 31;
    const int i   = iq * 8 + il;

    __shared__ float qs[32][8];
    __shared__ float ks[32][32];

    const float* __restrict__ qb = g_q + (size_t)b * F_OUT;
    const float* __restrict__ kb = g_k + (size_t)b * F_OUT;

    float z = 0.0f;
    for (int hc = 0; hc < 16; hc++) {
        {
            int hh = tid >> 3, ii = tid & 7;
            qs[hh][ii] = qb[(size_t)(hc * 32 + hh) * 32 + iq * 8 + ii];
            #pragma unroll
            for (int r = 0; r < 4; r++) {
                int idx = tid + r * 256;
                int hh2 = idx >> 5, jj = idx & 31;
                ks[hh2][jj] = kb[(size_t)(hc * 32 + hh2) * 32 + jj];
            }
        }
        __syncthreads();
        #pragma unroll
        for (int hh = 0; hh < 32; hh++)
            z += __expf(ATTN_SCALE * qs[hh][il] * ks[hh][j]);
        __syncthreads();
    }
    g_rzt[(size_t)b * 1024 + j * 32 + i] = 1.0f / z;
}

// ---------------------------------------------------------------------------
// Kernel 3: out[b,h,i] = sum_j exp(c*q_i*k_j) * rZ[b,i,j] * v[b,h,j]
// (k,v) staged in SMEM as float2 (LDS.64 broadcast per j), rz tile staged.
// ---------------------------------------------------------------------------
__global__ void attn_o_kernel(float* __restrict__ out) {
    __shared__ float2 kvs[8][32];
    __shared__ float  rzs[1024];

    const int b    = blockIdx.y;
    const int tid  = threadIdx.x;
    const int wl   = tid >> 5;
    const int lane = tid & 31;
    const int h    = blockIdx.x * 8 + wl;

    const size_t base = (size_t)b * F_OUT + (size_t)h * 32;

    {
        float kk = g_k[base + lane];
        float vv = g_v[base + lane];
        kvs[wl][lane] = make_float2(kk, vv);
        #pragma unroll
        for (int r = 0; r < 4; r++)
            rzs[tid + r * 256] = g_rzt[(size_t)b * 1024 + tid + r * 256];
    }
    const float qv = g_q[base + lane] * ATTN_SCALE;
    __syncthreads();

    float accv = 0.0f;
    #pragma unroll
    for (int j = 0; j < 32; j++) {
        float2 kv = kvs[wl][j];                 // LDS.64 broadcast
        accv += __expf(qv * kv.x) * kv.y * rzs[j * 32 + lane];
    }
    out[((size_t)b * HEADS + h) * 32 + lane] = accv;
}

// ---------------------------------------------------------------------------
extern "C" void kernel_launch(void* const* d_in, const int* in_sizes, int n_in,
                              void* d_out, int out_size) {
    const float* x  = (const float*)d_in[0];
    const float* Wq = (const float*)d_in[1];
    const float* bq = (const float*)d_in[2];
    const float* Wk = (const float*)d_in[3];
    const float* bk = (const float*)d_in[4];
    const float* Wv = (const float*)d_in[5];
    const float* bv = (const float*)d_in[6];
    // d_in[7] (tw): constant along softmax axis (heads) -> cancels; unused.
    (void)in_sizes; (void)n_in; (void)out_size;

    cudaFuncSetAttribute(qkv_gemm_kernel,
                         cudaFuncAttributeMaxDynamicSharedMemorySize, SMEM_BYTES);

    round_x_kernel<<<256, 256>>>((const float4*)x);
    qkv_gemm_kernel<<<dim3(F_OUT / MT, 3), 128, SMEM_BYTES>>>(Wq, bq, Wk, bk, Wv, bv);
    attn_z_kernel<<<dim3(32, 4), 256>>>();
    attn_o_kernel<<<dim3(64, 32), 256>>>((float*)d_out);
}

// round 13
// speedup vs baseline: 1.3089x; 1.0195x over previous
#include <cuda_runtime.h>
#include <cstdint>

#define F_IN   8192
#define F_OUT  16384
#define BATCH  32
#define HEADS  512

// Scratch (static __device__ — allocation-free per harness rules)
__device__ float g_q[BATCH * F_OUT];
__device__ float g_k[BATCH * F_OUT];
__device__ float g_v[BATCH * F_OUT];
__device__ float g_rzt[BATCH * 32 * 32]; // 1/Z transposed: [b][j][i]

__device__ __forceinline__ uint32_t tf32_rna(float f) {
    uint32_t u;
    asm("cvt.rna.tf32.f32 %0, %1;" : "=r"(u) : "f"(f));
    return u;
}

__device__ __forceinline__ float ex2(float x) {
    float r;
    asm("ex2.approx.f32 %0, %1;" : "=f"(r) : "f"(x));
    return r;
}

__device__ __forceinline__ float gelu_exact(float v) {
    return 0.5f * v * (1.0f + erff(v * 0.70710678118654752f));
}

// ---------------------------------------------------------------------------
// Kernel 1: QKV GEMM (R5-proven pipeline). Transposed:
// D^T[m][b] = sum_k W[m][k]*x[b][k]
//   A (M-side) = W : streamed, coalesced cp.async -> SMEM (read once)
//   B (N-side) = x : RAW x staged per chunk; RNA-rounded to tf32 at
//                    fragment load (removes the separate round_x kernel;
//                    identical numerics — same cvt.rna on same values).
// CTA: 128 thr / 4 warps, M-tile 128 (warp m32n32), N=32, K-chunk 32,
// 3 stages, wait_group 2 steady-state, stage AFTER compute.
// Grid 384 CTAs @ occ 3 -> all resident in ONE wave.
// k-permutation inside each k8 (logical tq -> phys 2tq, tq+4 -> 2tq+1) on
// BOTH operands => aligned LDS.64 fragments, conflict-free (RS=40 pad).
// ---------------------------------------------------------------------------
#define MMA_TF32(d, a0,a1,a2,a3, b0,b1)                                     \
    asm volatile("mma.sync.aligned.m16n8k8.row.col.f32.tf32.tf32.f32 "      \
        "{%0,%1,%2,%3}, {%4,%5,%6,%7}, {%8,%9}, {%0,%1,%2,%3};"             \
        : "+f"(d[0]), "+f"(d[1]), "+f"(d[2]), "+f"(d[3])                    \
        : "r"(a0), "r"(a1), "r"(a2), "r"(a3), "r"(b0), "r"(b1))

#define KC        32            // K-chunk
#define RS        40            // row stride in floats (32 + 8 pad)
#define MT        128           // CTA M-tile (rows of W)
#define NSTAGE    3
#define WSF       (MT * RS)     // 5120 floats per W stage
#define XSF       (BATCH * RS)  // 1280 floats per x stage
#define STAGEF    (WSF + XSF)   // 6400 floats per stage
#define SMEM_BYTES (NSTAGE * STAGEF * 4)   // 76800 B

__device__ __forceinline__ void cp16(float* dst, const float* src) {
    uint32_t d = (uint32_t)__cvta_generic_to_shared(dst);
    asm volatile("cp.async.cg.shared.global [%0], [%1], 16;" :: "r"(d), "l"(src));
}

__global__ __launch_bounds__(128, 3)
void qkv_gemm_kernel(const float* __restrict__ x,
                     const float* __restrict__ Wq, const float* __restrict__ bq,
                     const float* __restrict__ Wk, const float* __restrict__ bk,
                     const float* __restrict__ Wv, const float* __restrict__ bv) {
    extern __shared__ float smem[];

    const float* W; const float* bias; float* out;
    if (blockIdx.y == 0)      { W = Wq; bias = bq; out = g_q; }
    else if (blockIdx.y == 1) { W = Wk; bias = bk; out = g_k; }
    else                      { W = Wv; bias = bv; out = g_v; }

    const int tid  = threadIdx.x;
    const int warp = tid >> 5;
    const int lane = tid & 31;
    const int g    = lane >> 2;       // groupID (0..7)
    const int tq   = lane & 3;        // thread-in-group (0..3)
    const int mb   = blockIdx.x * MT; // CTA's first W row

    float acc[2][4][4];               // [m16-subtile][n-tile(batch/8)][frag]
    #pragma unroll
    for (int a = 0; a < 2; a++)
        #pragma unroll
        for (int b = 0; b < 4; b++)
            #pragma unroll
            for (int r = 0; r < 4; r++) acc[a][b][r] = 0.0f;

    // stage one K-chunk: W tile 128x32 + x tile 32x32, both coalesced
    auto stage = [&](int s, int c) {
        float* ws = smem + s * STAGEF;
        float* xs = ws + WSF;
        const int kc = c * KC;
        #pragma unroll
        for (int r = 0; r < 8; r++) {
            int idx = tid + r * 128;            // 1024 float4
            int row = idx >> 3;
            int c4  = idx & 7;
            cp16(&ws[row * RS + c4 * 4],
                 W + (size_t)(mb + row) * F_IN + kc + c4 * 4);
        }
        #pragma unroll
        for (int r = 0; r < 2; r++) {
            int idx = tid + r * 128;            // 256 float4
            int b   = idx >> 3;
            int c4  = idx & 7;
            cp16(&xs[b * RS + c4 * 4],
                 x + (size_t)b * F_IN + kc + c4 * 4);
        }
        asm volatile("cp.async.commit_group;");
    };

    stage(0, 0); stage(1, 1); stage(2, 2);

    const int NCHUNK = F_IN / KC;     // 256
    for (int c = 0; c < NCHUNK; c++) {
        const int rem = NCHUNK - 1 - c;
        if (rem >= 2)      asm volatile("cp.async.wait_group 2;");
        else if (rem == 1) asm volatile("cp.async.wait_group 1;");
        else               asm volatile("cp.async.wait_group 0;");
        __syncthreads();

        const float* ws = smem + (c % NSTAGE) * STAGEF;
        const float* xs = ws + WSF;

        #pragma unroll
        for (int s = 0; s < 4; s++) {
            const int kp = 8 * s + 2 * tq;    // physical k offset in chunk

            // A (W) fragments: two m16 subtiles, rows warp*32 + {g,g+8,g+16,g+24}
            uint32_t A[2][4];
            #pragma unroll
            for (int mt = 0; mt < 2; mt++) {
                const int r0 = warp * 32 + mt * 16 + g;
                float2 lo = *reinterpret_cast<const float2*>(&ws[r0 * RS + kp]);
                float2 hi = *reinterpret_cast<const float2*>(&ws[(r0 + 8) * RS + kp]);
                A[mt][0] = tf32_rna(lo.x);   // a0: (m=g,   k'=tq)
                A[mt][1] = tf32_rna(hi.x);   // a1: (m=g+8, k'=tq)
                A[mt][2] = tf32_rna(lo.y);   // a2: (m=g,   k'=tq+4)
                A[mt][3] = tf32_rna(hi.y);   // a3: (m=g+8, k'=tq+4)
            }

            // B (x^T) fragments: n = batch, 4 n-tiles of 8, RNA inline
            uint32_t B[4][2];
            #pragma unroll
            for (int j = 0; j < 4; j++) {
                float2 bvf = *reinterpret_cast<const float2*>(&xs[(j * 8 + g) * RS + kp]);
                B[j][0] = tf32_rna(bvf.x);
                B[j][1] = tf32_rna(bvf.y);
            }

            #pragma unroll
            for (int mt = 0; mt < 2; mt++)
                #pragma unroll
                for (int j = 0; j < 4; j++)
                    MMA_TF32(acc[mt][j], A[mt][0], A[mt][1], A[mt][2], A[mt][3],
                             B[j][0], B[j][1]);
        }

        __syncthreads();                      // all reads of buf done
        if (c + NSTAGE < NCHUNK) stage(c % NSTAGE, c + NSTAGE);
    }

    // Epilogue: bias + exact GELU, store transposed into [batch][F_OUT]
    #pragma unroll
    for (int mt = 0; mt < 2; mt++) {
        const int r0 = mb + warp * 32 + mt * 16 + g;   // output feature index
        const float bia0 = bias[r0];
        const float bia1 = bias[r0 + 8];
        #pragma unroll
        for (int j = 0; j < 4; j++) {
            const int bt = j * 8 + 2 * tq;             // batch index
            out[(size_t)bt       * F_OUT + r0    ] = gelu_exact(acc[mt][j][0] + bia0);
            out[(size_t)(bt + 1) * F_OUT + r0    ] = gelu_exact(acc[mt][j][1] + bia0);
            out[(size_t)bt       * F_OUT + r0 + 8] = gelu_exact(acc[mt][j][2] + bia1);
            out[(size_t)(bt + 1) * F_OUT + r0 + 8] = gelu_exact(acc[mt][j][3] + bia1);
        }
    }
}

// ---------------------------------------------------------------------------
// Kernel 2: softmax denominators over the HEADS axis (bias cancels).
// rZt[b][j][i] = 1 / sum_h exp(c * q[b,h,i] * k[b,h,j])
// Barrier-free (R8-proven): one-shot staging (k 64KB + q slice 16KB), q
// pre-scaled by c*log2(e); inner loop FMUL + EX2 + FADD over 512 heads.
// ---------------------------------------------------------------------------
#define ATTN_SCALE 0.17677669529663687f   // 1/sqrt(32)
#define SCALE_L2E  (0.17677669529663687f * 1.4426950408889634f)
#define Z_SMEM (512 * 8 * 4 + 512 * 32 * 4)   // 81920 B

__global__ void attn_z_kernel() {
    extern __shared__ float zsm[];
    float* qs = zsm;              // [512][8], pre-scaled
    float* ks = zsm + 512 * 8;    // [512][32]

    const int b  = blockIdx.x;
    const int iq = blockIdx.y;
    const int tid = threadIdx.x;
    const int il  = tid >> 5;
    const int j   = tid & 31;
    const int i   = iq * 8 + il;

    const float4* __restrict__ qb4 = (const float4*)(g_q + (size_t)b * F_OUT);
    const float4* __restrict__ kb4 = (const float4*)(g_k + (size_t)b * F_OUT);

    // ks = k[b] verbatim (same layout): 4096 float4
    #pragma unroll
    for (int r = 0; r < 16; r++) {
        int idx = tid + r * 256;
        ((float4*)ks)[idx] = kb4[idx];
    }
    // qs[h][0..7] = q[b][h*32 + iq*8 .. +8] * SCALE_L2E: 1024 float4
    #pragma unroll
    for (int r = 0; r < 4; r++) {
        int idx = tid + r * 256;
        int h = idx >> 1, u = idx & 1;
        float4 qv = qb4[h * 8 + iq * 2 + u];
        qv.x *= SCALE_L2E; qv.y *= SCALE_L2E;
        qv.z *= SCALE_L2E; qv.w *= SCALE_L2E;
        ((float4*)qs)[idx] = qv;
    }
    __syncthreads();

    float z = 0.0f;
    #pragma unroll 8
    for (int h = 0; h < 512; h++)
        z += ex2(qs[h * 8 + il] * ks[h * 32 + j]);

    g_rzt[(size_t)b * 1024 + j * 32 + i] = 1.0f / z;
}

// ---------------------------------------------------------------------------
// Kernel 3: out[b,h,i] = sum_j exp(c*q_i*k_j) * rZ[b,i,j] * v[b,h,j]
// (k,v) staged in SMEM as float2 (LDS.64 broadcast per j), rz tile staged.
// q pre-scaled by c*log2(e); inner is FMUL + EX2 + FMUL + FFMA.
// ---------------------------------------------------------------------------
__global__ void attn_o_kernel(float* __restrict__ out) {
    __shared__ float2 kvs[8][32];
    __shared__ float  rzs[1024];

    const int b    = blockIdx.y;
    const int tid  = threadIdx.x;
    const int wl   = tid >> 5;
    const int lane = tid & 31;
    const int h    = blockIdx.x * 8 + wl;

    const size_t base = (size_t)b * F_OUT + (size_t)h * 32;

    {
        float kk = g_k[base + lane];
        float vv = g_v[base + lane];
        kvs[wl][lane] = make_float2(kk, vv);
        #pragma unroll
        for (int r = 0; r < 4; r++)
            rzs[tid + r * 256] = g_rzt[(size_t)b * 1024 + tid + r * 256];
    }
    const float qv = g_q[base + lane] * SCALE_L2E;
    __syncthreads();

    float accv = 0.0f;
    #pragma unroll
    for (int j = 0; j < 32; j++) {
        float2 kv = kvs[wl][j];                 // LDS.64 broadcast
        accv += ex2(qv * kv.x) * kv.y * rzs[j * 32 + lane];
    }
    out[((size_t)b * HEADS + h) * 32 + lane] = accv;
}

// ---------------------------------------------------------------------------
extern "C" void kernel_launch(void* const* d_in, const int* in_sizes, int n_in,
                              void* d_out, int out_size) {
    const float* x  = (const float*)d_in[0];
    const float* Wq = (const float*)d_in[1];
    const float* bq = (const float*)d_in[2];
    const float* Wk = (const float*)d_in[3];
    const float* bk = (const float*)d_in[4];
    const float* Wv = (const float*)d_in[5];
    const float* bv = (const float*)d_in[6];
    // d_in[7] (tw): constant along softmax axis (heads) -> cancels; unused.
    (void)in_sizes; (void)n_in; (void)out_size;

    cudaFuncSetAttribute(qkv_gemm_kernel,
                         cudaFuncAttributeMaxDynamicSharedMemorySize, SMEM_BYTES);
    cudaFuncSetAttribute(attn_z_kernel,
                         cudaFuncAttributeMaxDynamicSharedMemorySize, Z_SMEM);

    qkv_gemm_kernel<<<dim3(F_OUT / MT, 3), 128, SMEM_BYTES>>>(x, Wq, bq, Wk, bk, Wv, bv);
    attn_z_kernel<<<dim3(32, 4), 256, Z_SMEM>>>();
    attn_o_kernel<<<dim3(64, 32), 256>>>((float*)d_out);
}